// round 12
// baseline (speedup 1.0000x reference)
#include <cuda_runtime.h>
#include <cstdint>

#define TT 2048
#define BB 8
#define CC 1024
#define HH 64
#define NROWS (BB*TT)

__device__ float g_q[NROWS*HH];
__device__ float g_k[NROWS*HH];
__device__ float g_v[NROWS*HH];

__device__ __forceinline__ float to_tf32(float f) {
    uint32_t u;
    asm("cvt.rna.tf32.f32 %0, %1;" : "=r"(u) : "f"(f));
    return __uint_as_float(u);
}

__device__ __forceinline__ void mma_tf32(float c[4],
    uint32_t a0, uint32_t a1, uint32_t a2, uint32_t a3,
    uint32_t b0, uint32_t b1)
{
    asm volatile(
        "mma.sync.aligned.m16n8k8.row.col.f32.tf32.tf32.f32 "
        "{%0,%1,%2,%3}, {%4,%5,%6,%7}, {%8,%9}, {%0,%1,%2,%3};"
        : "+f"(c[0]), "+f"(c[1]), "+f"(c[2]), "+f"(c[3])
        : "r"(a0), "r"(a1), "r"(a2), "r"(a3), "r"(b0), "r"(b1));
}

__device__ __forceinline__ void cp_async16(uint32_t dst, const void* src) {
    asm volatile("cp.async.cg.shared.global [%0], [%1], 16;" :: "r"(dst), "l"(src));
}
__device__ __forceinline__ void cp_commit() {
    asm volatile("cp.async.commit_group;" ::: "memory");
}
__device__ __forceinline__ void cp_wait0() {
    asm volatile("cp.async.wait_group 0;" ::: "memory");
}
__device__ __forceinline__ void cp_wait1() {
    asm volatile("cp.async.wait_group 1;" ::: "memory");
}
__device__ __forceinline__ uint32_t smem_u32(const void* p) {
    uint32_t a;
    asm("{ .reg .u64 t; cvta.to.shared.u64 t, %1; cvt.u32.u64 %0, t; }"
        : "=r"(a) : "l"(p));
    return a;
}

// ---------------------------------------------------------------------------
// QKV GEMM via tf32 mma.sync. NEW: epilogue rounds outputs to tf32 (rna) so
// the attention kernel can consume raw bits with zero further conversion.
// ---------------------------------------------------------------------------
__global__ __launch_bounds__(256) void qkv_mma_kernel(
    const float* __restrict__ x,
    const float* __restrict__ Wq,
    const float* __restrict__ Wk,
    const float* __restrict__ Wv)
{
    __shared__ __align__(16) float xs[128][36];
    __shared__ __align__(16) float ws[32][104];

    const int tid  = threadIdx.x;
    const int warp = tid >> 5;
    const int lane = tid & 31;
    const int bm   = blockIdx.x >> 1;
    const int bn   = blockIdx.x & 1;
    const int row0 = bm * 128;
    const int wm   = warp >> 1;
    const int wn   = warp & 1;
    const int g    = lane >> 2;
    const int tg   = lane & 3;

    float c[2][6][4];
#pragma unroll
    for (int mf = 0; mf < 2; mf++)
#pragma unroll
        for (int nf = 0; nf < 6; nf++)
#pragma unroll
            for (int i = 0; i < 4; i++) c[mf][nf][i] = 0.f;

    float4 xr[4], wr[3];

#pragma unroll
    for (int it = 0; it < 4; it++) {
        int f = it * 256 + tid;
        int r = f >> 3, c4 = f & 7;
        xr[it] = *(const float4*)(x + (size_t)(row0 + r) * CC + c4 * 4);
    }
#pragma unroll
    for (int it = 0; it < 3; it++) {
        int f = it * 256 + tid;
        int k = f / 24, c4 = f % 24;
        int n = bn * 96 + c4 * 4;
        const float* Wsrc = (n < 64) ? Wq : ((n < 128) ? Wk : Wv);
        wr[it] = *(const float4*)(Wsrc + (size_t)k * HH + (n & 63));
    }

    for (int k0 = 0; k0 < CC; k0 += 32) {
        __syncthreads();

#pragma unroll
        for (int it = 0; it < 4; it++) {
            int f = it * 256 + tid;
            int r = f >> 3, c4 = f & 7;
            float4 v = xr[it];
            xs[r][c4 * 4 + 0] = to_tf32(v.x);
            xs[r][c4 * 4 + 1] = to_tf32(v.y);
            xs[r][c4 * 4 + 2] = to_tf32(v.z);
            xs[r][c4 * 4 + 3] = to_tf32(v.w);
        }
#pragma unroll
        for (int it = 0; it < 3; it++) {
            int f = it * 256 + tid;
            int k = f / 24, c4 = f % 24;
            float4 v = wr[it];
            ws[k][c4 * 4 + 0] = to_tf32(v.x);
            ws[k][c4 * 4 + 1] = to_tf32(v.y);
            ws[k][c4 * 4 + 2] = to_tf32(v.z);
            ws[k][c4 * 4 + 3] = to_tf32(v.w);
        }
        __syncthreads();

        const int kn = k0 + 32;
        if (kn < CC) {
#pragma unroll
            for (int it = 0; it < 4; it++) {
                int f = it * 256 + tid;
                int r = f >> 3, c4 = f & 7;
                xr[it] = *(const float4*)(x + (size_t)(row0 + r) * CC + kn + c4 * 4);
            }
#pragma unroll
            for (int it = 0; it < 3; it++) {
                int f = it * 256 + tid;
                int k = f / 24, c4 = f % 24;
                int n = bn * 96 + c4 * 4;
                const float* Wsrc = (n < 64) ? Wq : ((n < 128) ? Wk : Wv);
                wr[it] = *(const float4*)(Wsrc + (size_t)(kn + k) * HH + (n & 63));
            }
        }

#pragma unroll
        for (int ks = 0; ks < 4; ks++) {
            uint32_t a[2][4];
#pragma unroll
            for (int mf = 0; mf < 2; mf++) {
                int r = wm * 32 + mf * 16 + g;
                a[mf][0] = __float_as_uint(xs[r    ][ks * 8 + tg    ]);
                a[mf][1] = __float_as_uint(xs[r + 8][ks * 8 + tg    ]);
                a[mf][2] = __float_as_uint(xs[r    ][ks * 8 + tg + 4]);
                a[mf][3] = __float_as_uint(xs[r + 8][ks * 8 + tg + 4]);
            }
            uint32_t bf[6][2];
#pragma unroll
            for (int nf = 0; nf < 6; nf++) {
                int n = wn * 48 + nf * 8 + g;
                bf[nf][0] = __float_as_uint(ws[ks * 8 + tg    ][n]);
                bf[nf][1] = __float_as_uint(ws[ks * 8 + tg + 4][n]);
            }
#pragma unroll
            for (int mf = 0; mf < 2; mf++)
#pragma unroll
                for (int nf = 0; nf < 6; nf++)
                    mma_tf32(c[mf][nf], a[mf][0], a[mf][1], a[mf][2], a[mf][3],
                             bf[nf][0], bf[nf][1]);
        }
    }

    // epilogue: round to tf32 (rna) so downstream MMA truncation is lossless
#pragma unroll
    for (int mf = 0; mf < 2; mf++) {
        int row = row0 + wm * 32 + mf * 16 + g;
#pragma unroll
        for (int nf = 0; nf < 6; nf++) {
            int n = bn * 96 + wn * 48 + nf * 8 + 2 * tg;
            float* dst = (n < 64) ? g_q : ((n < 128) ? g_k : g_v);
            int h = n & 63;
            *(float2*)(dst + (size_t)row * HH + h) =
                make_float2(to_tf32(c[mf][nf][0]), to_tf32(c[mf][nf][1]));
            *(float2*)(dst + (size_t)(row + 8) * HH + h) =
                make_float2(to_tf32(c[mf][nf][2]), to_tf32(c[mf][nf][3]));
        }
    }
}

// ---------------------------------------------------------------------------
// Attention via tf32 mma.sync, cp.async double-buffered K/V.
// Block = 64-query qtile, 4 warps, each warp owns 16 rows x all 64 keys.
// Dynamic smem: ks[2][64*64] | vs[2][64*64] | ps[64*68]  (82,944 B).
// Q fragments loaded directly from gmem (L2-resident, tf32-prerounded).
// No register prefetch -> no spills (R10 had regs=255 + LDL/STL).
// ---------------------------------------------------------------------------
__global__ __launch_bounds__(128) void attn_kernel(
    const float* __restrict__ rbias,
    float* __restrict__ out)
{
    extern __shared__ __align__(16) float dyn[];
    float* ps = dyn + 16384;                  // 64 x 68 P-bounce
    const uint32_t sbase = smem_u32(dyn);

    const int tid  = threadIdx.x;
    const int w    = tid >> 5;
    const int lane = tid & 31;
    const int g    = lane >> 2;
    const int tg   = lane & 3;
    const int b    = blockIdx.x & 7;
    const int qt   = 31 - (blockIdx.x >> 3);  // biggest first
    const int i0   = qt * 64;
    const float scale = 0.03125f;             // 1024^-0.5

    const int key_st = (tid >> 4);            // staging key 0..63 base (p*8 rows)
    const int h4_st  = tid & 15;

    // issue one 64-key K/V tile into buffer `buf` via cp.async
    auto issue_kv = [&](int s0, int buf) {
        const float* kp = g_k + ((size_t)b * TT + s0) * HH;
        const float* vp = g_v + ((size_t)b * TT + s0) * HH;
        const uint32_t kd = sbase + buf * 16384;
        const uint32_t vd = sbase + 32768 + buf * 16384;
#pragma unroll
        for (int p = 0; p < 8; p++) {
            int key = key_st + p * 8;
            cp_async16(kd + key * 256 + ((h4_st ^ (key & 7)) << 4),
                       kp + key * HH + h4_st * 4);
            cp_async16(vd + key * 256 + ((h4_st ^ ((key & 3) << 1)) << 4),
                       vp + key * HH + h4_st * 4);
        }
    };

    // start tile 0 immediately
    issue_kv(0, 0);
    cp_commit();

    // ---- Q fragments straight from gmem (already tf32-rounded) ----
    const int rl = 16 * w + g;
    const float* qg = g_q + ((size_t)b * TT + i0) * HH;
    uint32_t qa[8][4];
#pragma unroll
    for (int ks = 0; ks < 8; ks++) {
        qa[ks][0] = __float_as_uint(qg[(size_t)rl      * HH + 8 * ks + tg    ]);
        qa[ks][1] = __float_as_uint(qg[(size_t)(rl + 8)* HH + 8 * ks + tg    ]);
        qa[ks][2] = __float_as_uint(qg[(size_t)rl      * HH + 8 * ks + tg + 4]);
        qa[ks][3] = __float_as_uint(qg[(size_t)(rl + 8)* HH + 8 * ks + tg + 4]);
    }

    float o[8][4];
#pragma unroll
    for (int nf = 0; nf < 8; nf++)
#pragma unroll
        for (int i = 0; i < 4; i++) o[nf][i] = 0.f;
    float m0 = -1e30f, m1 = -1e30f, l0 = 0.f, l1 = 0.f;

    const int irow0 = i0 + rl;
    const int irow1 = irow0 + 8;
    const int nt = qt + 1;

    for (int it = 0; it < nt; it++) {
        const int s0  = it * 64;
        const int buf = it & 1;

        __syncthreads();   // all warps done with buf^1's previous contents

        if (it + 1 < nt) {
            issue_kv(s0 + 64, buf ^ 1);
            cp_commit();
            cp_wait1();    // tile `it` (older group) complete
        } else {
            cp_wait0();
        }

        // rbias for this lane's 2x16 slice (L2-resident, overlaps S-GEMM)
        float2 rb0[8], rb1[8];
        {
            const float* rp0 = rbias + (size_t)irow0 * TT + s0 + 2 * tg;
            const float* rp1 = rp0 + 8 * TT;
#pragma unroll
            for (int nf = 0; nf < 8; nf++) {
                rb0[nf] = *(const float2*)(rp0 + 8 * nf);
                rb1[nf] = *(const float2*)(rp1 + 8 * nf);
            }
        }
        __syncthreads();   // staged K/V visible to all warps

        const float* kb = dyn + buf * 4096;
        const float* vb = dyn + 8192 + buf * 4096;

        // ---- S-GEMM ----
        float sc[8][4];
#pragma unroll
        for (int nf = 0; nf < 8; nf++)
#pragma unroll
            for (int i = 0; i < 4; i++) sc[nf][i] = 0.f;

#pragma unroll
        for (int ks = 0; ks < 8; ks++) {
#pragma unroll
            for (int nf = 0; nf < 8; nf++) {
                int key = 8 * nf + g;
                uint32_t kb0 = __float_as_uint(kb[key * 64 + (((2 * ks    ) ^ g) << 2) + tg]);
                uint32_t kb1 = __float_as_uint(kb[key * 64 + (((2 * ks + 1) ^ g) << 2) + tg]);
                mma_tf32(sc[nf], qa[ks][0], qa[ks][1], qa[ks][2], qa[ks][3], kb0, kb1);
            }
        }

        // ---- bias + mask ----
#pragma unroll
        for (int nf = 0; nf < 8; nf++) {
            int c0 = s0 + 8 * nf + 2 * tg;
            {
                float rbx = rb0[nf].x, rby = rb0[nf].y;
                bool a0 = (c0     == irow0) || ((c0     < irow0) && (rbx > 0.f));
                bool a1 = (c0 + 1 == irow0) || ((c0 + 1 < irow0) && (rby > 0.f));
                sc[nf][0] = a0 ? sc[nf][0] * scale + rbx : -1e30f;
                sc[nf][1] = a1 ? sc[nf][1] * scale + rby : -1e30f;
            }
            {
                float rbx = rb1[nf].x, rby = rb1[nf].y;
                bool a0 = (c0     == irow1) || ((c0     < irow1) && (rbx > 0.f));
                bool a1 = (c0 + 1 == irow1) || ((c0 + 1 < irow1) && (rby > 0.f));
                sc[nf][2] = a0 ? sc[nf][2] * scale + rbx : -1e30f;
                sc[nf][3] = a1 ? sc[nf][3] * scale + rby : -1e30f;
            }
        }

        // ---- online softmax (warp-local) ----
        float t0 = -1e30f, t1 = -1e30f;
#pragma unroll
        for (int nf = 0; nf < 8; nf++) {
            t0 = fmaxf(t0, fmaxf(sc[nf][0], sc[nf][1]));
            t1 = fmaxf(t1, fmaxf(sc[nf][2], sc[nf][3]));
        }
        t0 = fmaxf(t0, __shfl_xor_sync(0xffffffffu, t0, 1));
        t0 = fmaxf(t0, __shfl_xor_sync(0xffffffffu, t0, 2));
        t1 = fmaxf(t1, __shfl_xor_sync(0xffffffffu, t1, 1));
        t1 = fmaxf(t1, __shfl_xor_sync(0xffffffffu, t1, 2));

        float mn0 = fmaxf(m0, t0), mn1 = fmaxf(m1, t1);
        float f0 = __expf(m0 - mn0), f1 = __expf(m1 - mn1);
        m0 = mn0; m1 = mn1;

        float s0sum = 0.f, s1sum = 0.f;
#pragma unroll
        for (int nf = 0; nf < 8; nf++) {
            float e;
            e = (sc[nf][0] > -1e29f) ? __expf(sc[nf][0] - mn0) : 0.f; sc[nf][0] = e; s0sum += e;
            e = (sc[nf][1] > -1e29f) ? __expf(sc[nf][1] - mn0) : 0.f; sc[nf][1] = e; s0sum += e;
            e = (sc[nf][2] > -1e29f) ? __expf(sc[nf][2] - mn1) : 0.f; sc[nf][2] = e; s1sum += e;
            e = (sc[nf][3] > -1e29f) ? __expf(sc[nf][3] - mn1) : 0.f; sc[nf][3] = e; s1sum += e;
        }
        s0sum += __shfl_xor_sync(0xffffffffu, s0sum, 1);
        s0sum += __shfl_xor_sync(0xffffffffu, s0sum, 2);
        s1sum += __shfl_xor_sync(0xffffffffu, s1sum, 1);
        s1sum += __shfl_xor_sync(0xffffffffu, s1sum, 2);
        l0 = l0 * f0 + s0sum;
        l1 = l1 * f1 + s1sum;

#pragma unroll
        for (int nf = 0; nf < 8; nf++) {
            o[nf][0] *= f0; o[nf][1] *= f0;
            o[nf][2] *= f1; o[nf][3] *= f1;
        }

        // ---- write P (tf32) into ps (warp-private rows) ----
#pragma unroll
        for (int nf = 0; nf < 8; nf++) {
            *(float2*)&ps[rl * 68 + 8 * nf + 2 * tg] =
                make_float2(to_tf32(sc[nf][0]), to_tf32(sc[nf][1]));
            *(float2*)&ps[(rl + 8) * 68 + 8 * nf + 2 * tg] =
                make_float2(to_tf32(sc[nf][2]), to_tf32(sc[nf][3]));
        }
        __syncwarp();

        // ---- O-GEMM: O += P * V ----
#pragma unroll
        for (int ks = 0; ks < 8; ks++) {
            uint32_t pa0 = __float_as_uint(ps[rl * 68       + 8 * ks + tg    ]);
            uint32_t pa1 = __float_as_uint(ps[(rl + 8) * 68 + 8 * ks + tg    ]);
            uint32_t pa2 = __float_as_uint(ps[rl * 68       + 8 * ks + tg + 4]);
            uint32_t pa3 = __float_as_uint(ps[(rl + 8) * 68 + 8 * ks + tg + 4]);
            const int key0 = 8 * ks + tg, key1 = key0 + 4;
#pragma unroll
            for (int nf = 0; nf < 8; nf++) {
                int cv = (((2 * nf + (g >> 2)) ^ (tg << 1)) << 2) + (g & 3);
                uint32_t vb0 = __float_as_uint(vb[key0 * 64 + cv]);
                uint32_t vb1 = __float_as_uint(vb[key1 * 64 + cv]);
                mma_tf32(o[nf], pa0, pa1, pa2, pa3, vb0, vb1);
            }
        }
    }

    // ---- epilogue ----
    const float inv0 = 1.f / l0;
    const float inv1 = 1.f / l1;
    float* op0 = out + ((size_t)b * TT + irow0) * HH + 2 * tg;
    float* op1 = out + ((size_t)b * TT + irow1) * HH + 2 * tg;
#pragma unroll
    for (int nf = 0; nf < 8; nf++) {
        *(float2*)(op0 + 8 * nf) = make_float2(o[nf][0] * inv0, o[nf][1] * inv0);
        *(float2*)(op1 + 8 * nf) = make_float2(o[nf][2] * inv1, o[nf][3] * inv1);
    }
}

extern "C" void kernel_launch(void* const* d_in, const int* in_sizes, int n_in,
                              void* d_out, int out_size)
{
    (void)in_sizes; (void)n_in; (void)out_size;
    const float* x     = (const float*)d_in[0];
    const float* Wq    = (const float*)d_in[1];
    const float* Wk    = (const float*)d_in[2];
    const float* Wv    = (const float*)d_in[3];
    const float* rbias = (const float*)d_in[4];

    const int attn_smem = 2 * 16384 + 2 * 16384 + 64 * 68 * 4;  // 82,944 B
    cudaFuncSetAttribute(attn_kernel,
                         cudaFuncAttributeMaxDynamicSharedMemorySize, attn_smem);

    qkv_mma_kernel<<<256, 256>>>(x, Wq, Wk, Wv);
    attn_kernel<<<BB * 32, 128, attn_smem>>>(rbias, (float*)d_out);
}

// round 17
// speedup vs baseline: 1.3962x; 1.3962x over previous
#include <cuda_runtime.h>
#include <cstdint>

#define TT 2048
#define BB 8
#define CC 1024
#define HH 64
#define NROWS (BB*TT)
#define NJOBS 640

__device__ float g_q[NROWS*HH];
__device__ float g_k[NROWS*HH];
__device__ float g_v[NROWS*HH];
__device__ float  g_po[(size_t)4 * NROWS * HH];   // unnormalized partial O per chunk
__device__ float2 g_pml[4 * NROWS];               // (m, l) per chunk per row
__device__ int    g_ctr;

// Job table: (qt, chunk) pairs, biggest chunk first. 80 pairs x 8 batches = 640 jobs.
__constant__ uchar2 g_jobtab[80] = {
    // size 8, c0 (qt 7..31)
    {7,0},{8,0},{9,0},{10,0},{11,0},{12,0},{13,0},{14,0},{15,0},{16,0},{17,0},
    {18,0},{19,0},{20,0},{21,0},{22,0},{23,0},{24,0},{25,0},{26,0},{27,0},{28,0},
    {29,0},{30,0},{31,0},
    // size 8, c1 (qt 15..31)
    {15,1},{16,1},{17,1},{18,1},{19,1},{20,1},{21,1},{22,1},{23,1},{24,1},{25,1},
    {26,1},{27,1},{28,1},{29,1},{30,1},{31,1},
    // size 8, c2 (qt 23..31)
    {23,2},{24,2},{25,2},{26,2},{27,2},{28,2},{29,2},{30,2},{31,2},
    // size 8, c3
    {31,3},
    // sizes 7..1
    {6,0},{14,1},{22,2},{30,3},
    {5,0},{13,1},{21,2},{29,3},
    {4,0},{12,1},{20,2},{28,3},
    {3,0},{11,1},{19,2},{27,3},
    {2,0},{10,1},{18,2},{26,3},
    {1,0},{9,1},{17,2},{25,3},
    {0,0},{8,1},{16,2},{24,3},
};

__device__ __forceinline__ float to_tf32(float f) {
    uint32_t u;
    asm("cvt.rna.tf32.f32 %0, %1;" : "=r"(u) : "f"(f));
    return __uint_as_float(u);
}

__device__ __forceinline__ void mma_tf32(float c[4],
    uint32_t a0, uint32_t a1, uint32_t a2, uint32_t a3,
    uint32_t b0, uint32_t b1)
{
    asm volatile(
        "mma.sync.aligned.m16n8k8.row.col.f32.tf32.tf32.f32 "
        "{%0,%1,%2,%3}, {%4,%5,%6,%7}, {%8,%9}, {%0,%1,%2,%3};"
        : "+f"(c[0]), "+f"(c[1]), "+f"(c[2]), "+f"(c[3])
        : "r"(a0), "r"(a1), "r"(a2), "r"(a3), "r"(b0), "r"(b1));
}

__device__ __forceinline__ void cp_async16(uint32_t dst, const void* src) {
    asm volatile("cp.async.cg.shared.global [%0], [%1], 16;" :: "r"(dst), "l"(src));
}
__device__ __forceinline__ void cp_commit() {
    asm volatile("cp.async.commit_group;" ::: "memory");
}
__device__ __forceinline__ void cp_wait0() {
    asm volatile("cp.async.wait_group 0;" ::: "memory");
}
__device__ __forceinline__ void cp_wait1() {
    asm volatile("cp.async.wait_group 1;" ::: "memory");
}
__device__ __forceinline__ uint32_t smem_u32(const void* p) {
    uint32_t a;
    asm("{ .reg .u64 t; cvta.to.shared.u64 t, %1; cvt.u32.u64 %0, t; }"
        : "=r"(a) : "l"(p));
    return a;
}

__global__ void reset_ctr_kernel() { g_ctr = 0; }

// ---------------------------------------------------------------------------
// QKV GEMM via tf32 mma.sync (unchanged). Epilogue pre-rounds to tf32.
// ---------------------------------------------------------------------------
__global__ __launch_bounds__(256) void qkv_mma_kernel(
    const float* __restrict__ x,
    const float* __restrict__ Wq,
    const float* __restrict__ Wk,
    const float* __restrict__ Wv)
{
    __shared__ __align__(16) float xs[128][36];
    __shared__ __align__(16) float ws[32][104];

    const int tid  = threadIdx.x;
    const int warp = tid >> 5;
    const int lane = tid & 31;
    const int bm   = blockIdx.x >> 1;
    const int bn   = blockIdx.x & 1;
    const int row0 = bm * 128;
    const int wm   = warp >> 1;
    const int wn   = warp & 1;
    const int g    = lane >> 2;
    const int tg   = lane & 3;

    float c[2][6][4];
#pragma unroll
    for (int mf = 0; mf < 2; mf++)
#pragma unroll
        for (int nf = 0; nf < 6; nf++)
#pragma unroll
            for (int i = 0; i < 4; i++) c[mf][nf][i] = 0.f;

    float4 xr[4], wr[3];

#pragma unroll
    for (int it = 0; it < 4; it++) {
        int f = it * 256 + tid;
        int r = f >> 3, c4 = f & 7;
        xr[it] = *(const float4*)(x + (size_t)(row0 + r) * CC + c4 * 4);
    }
#pragma unroll
    for (int it = 0; it < 3; it++) {
        int f = it * 256 + tid;
        int k = f / 24, c4 = f % 24;
        int n = bn * 96 + c4 * 4;
        const float* Wsrc = (n < 64) ? Wq : ((n < 128) ? Wk : Wv);
        wr[it] = *(const float4*)(Wsrc + (size_t)k * HH + (n & 63));
    }

    for (int k0 = 0; k0 < CC; k0 += 32) {
        __syncthreads();

#pragma unroll
        for (int it = 0; it < 4; it++) {
            int f = it * 256 + tid;
            int r = f >> 3, c4 = f & 7;
            float4 v = xr[it];
            xs[r][c4 * 4 + 0] = to_tf32(v.x);
            xs[r][c4 * 4 + 1] = to_tf32(v.y);
            xs[r][c4 * 4 + 2] = to_tf32(v.z);
            xs[r][c4 * 4 + 3] = to_tf32(v.w);
        }
#pragma unroll
        for (int it = 0; it < 3; it++) {
            int f = it * 256 + tid;
            int k = f / 24, c4 = f % 24;
            float4 v = wr[it];
            ws[k][c4 * 4 + 0] = to_tf32(v.x);
            ws[k][c4 * 4 + 1] = to_tf32(v.y);
            ws[k][c4 * 4 + 2] = to_tf32(v.z);
            ws[k][c4 * 4 + 3] = to_tf32(v.w);
        }
        __syncthreads();

        const int kn = k0 + 32;
        if (kn < CC) {
#pragma unroll
            for (int it = 0; it < 4; it++) {
                int f = it * 256 + tid;
                int r = f >> 3, c4 = f & 7;
                xr[it] = *(const float4*)(x + (size_t)(row0 + r) * CC + kn + c4 * 4);
            }
#pragma unroll
            for (int it = 0; it < 3; it++) {
                int f = it * 256 + tid;
                int k = f / 24, c4 = f % 24;
                int n = bn * 96 + c4 * 4;
                const float* Wsrc = (n < 64) ? Wq : ((n < 128) ? Wk : Wv);
                wr[it] = *(const float4*)(Wsrc + (size_t)(kn + k) * HH + (n & 63));
            }
        }

#pragma unroll
        for (int ks = 0; ks < 4; ks++) {
            uint32_t a[2][4];
#pragma unroll
            for (int mf = 0; mf < 2; mf++) {
                int r = wm * 32 + mf * 16 + g;
                a[mf][0] = __float_as_uint(xs[r    ][ks * 8 + tg    ]);
                a[mf][1] = __float_as_uint(xs[r + 8][ks * 8 + tg    ]);
                a[mf][2] = __float_as_uint(xs[r    ][ks * 8 + tg + 4]);
                a[mf][3] = __float_as_uint(xs[r + 8][ks * 8 + tg + 4]);
            }
            uint32_t bf[6][2];
#pragma unroll
            for (int nf = 0; nf < 6; nf++) {
                int n = wn * 48 + nf * 8 + g;
                bf[nf][0] = __float_as_uint(ws[ks * 8 + tg    ][n]);
                bf[nf][1] = __float_as_uint(ws[ks * 8 + tg + 4][n]);
            }
#pragma unroll
            for (int mf = 0; mf < 2; mf++)
#pragma unroll
                for (int nf = 0; nf < 6; nf++)
                    mma_tf32(c[mf][nf], a[mf][0], a[mf][1], a[mf][2], a[mf][3],
                             bf[nf][0], bf[nf][1]);
        }
    }

#pragma unroll
    for (int mf = 0; mf < 2; mf++) {
        int row = row0 + wm * 32 + mf * 16 + g;
#pragma unroll
        for (int nf = 0; nf < 6; nf++) {
            int n = bn * 96 + wn * 48 + nf * 8 + 2 * tg;
            float* dst = (n < 64) ? g_q : ((n < 128) ? g_k : g_v);
            int h = n & 63;
            *(float2*)(dst + (size_t)row * HH + h) =
                make_float2(to_tf32(c[mf][nf][0]), to_tf32(c[mf][nf][1]));
            *(float2*)(dst + (size_t)(row + 8) * HH + h) =
                make_float2(to_tf32(c[mf][nf][2]), to_tf32(c[mf][nf][3]));
        }
    }
}

// ---------------------------------------------------------------------------
// Attention, split-KV persistent version.
// Persistent CTAs (grid 304) pull jobs (b, qt, chunk) from an atomic counter;
// each job processes <=8 KV tiles of one 64-row qtile and writes an
// UNNORMALIZED partial (o, m, l) to scratch. merge_kernel combines chunks.
// ---------------------------------------------------------------------------
__global__ __launch_bounds__(128) void attn_kernel(const float* __restrict__ rbias)
{
    extern __shared__ __align__(16) float dyn[];
    float* ps = dyn + 16384;                    // 64 x 68 P-bounce
    int*   jslot = (int*)(dyn + 16384 + 64 * 68);
    const uint32_t sbase = smem_u32(dyn);

    const int tid  = threadIdx.x;
    const int w    = tid >> 5;
    const int lane = tid & 31;
    const int g    = lane >> 2;
    const int tg   = lane & 3;
    const float scale = 0.03125f;               // 1024^-0.5

    const int key_st = (tid >> 4);
    const int h4_st  = tid & 15;
    const int rl = 16 * w + g;

    while (true) {
        if (tid == 0) *jslot = atomicAdd(&g_ctr, 1);
        __syncthreads();                        // broadcast + prev-job readers done
        const int j = *jslot;
        if (j >= NJOBS) return;

        const uchar2 qc = g_jobtab[j >> 3];
        const int b  = j & 7;
        const int qt = qc.x;
        const int ch = qc.y;
        const int i0 = qt << 6;
        const int t_begin = ch * 8;
        const int ntile   = min(8, (qt + 1) - t_begin);
        const int s_begin = t_begin * 64;

        // issue one 64-key K/V tile into buffer `buf`
        auto issue_kv = [&](int s0, int buf) {
            const float* kp = g_k + ((size_t)b * TT + s0) * HH;
            const float* vp = g_v + ((size_t)b * TT + s0) * HH;
            const uint32_t kd = sbase + buf * 16384;
            const uint32_t vd = sbase + 32768 + buf * 16384;
#pragma unroll
            for (int p = 0; p < 8; p++) {
                int key = key_st + p * 8;
                cp_async16(kd + key * 256 + ((h4_st ^ (key & 7)) << 4),
                           kp + key * HH + h4_st * 4);
                cp_async16(vd + key * 256 + ((h4_st ^ ((key & 3) << 1)) << 4),
                           vp + key * HH + h4_st * 4);
            }
        };

        issue_kv(s_begin, 0);
        cp_commit();

        // Q fragments straight from gmem (tf32-prerounded, L2-resident)
        const float* qg = g_q + ((size_t)b * TT + i0) * HH;
        uint32_t qa[8][4];
#pragma unroll
        for (int ks = 0; ks < 8; ks++) {
            qa[ks][0] = __float_as_uint(qg[(size_t)rl      * HH + 8 * ks + tg    ]);
            qa[ks][1] = __float_as_uint(qg[(size_t)(rl + 8)* HH + 8 * ks + tg    ]);
            qa[ks][2] = __float_as_uint(qg[(size_t)rl      * HH + 8 * ks + tg + 4]);
            qa[ks][3] = __float_as_uint(qg[(size_t)(rl + 8)* HH + 8 * ks + tg + 4]);
        }

        float o[8][4];
#pragma unroll
        for (int nf = 0; nf < 8; nf++)
#pragma unroll
            for (int i = 0; i < 4; i++) o[nf][i] = 0.f;
        float m0 = -1e30f, m1 = -1e30f, l0 = 0.f, l1 = 0.f;

        const int irow0 = i0 + rl;
        const int irow1 = irow0 + 8;

        for (int it = 0; it < ntile; it++) {
            const int s0  = s_begin + it * 64;
            const int buf = it & 1;

            __syncthreads();

            if (it + 1 < ntile) {
                issue_kv(s0 + 64, buf ^ 1);
                cp_commit();
                cp_wait1();
            } else {
                cp_wait0();
            }

            float2 rb0[8], rb1[8];
            {
                const float* rp0 = rbias + (size_t)irow0 * TT + s0 + 2 * tg;
                const float* rp1 = rp0 + 8 * TT;
#pragma unroll
                for (int nf = 0; nf < 8; nf++) {
                    rb0[nf] = *(const float2*)(rp0 + 8 * nf);
                    rb1[nf] = *(const float2*)(rp1 + 8 * nf);
                }
            }
            __syncthreads();

            const float* kb = dyn + buf * 4096;
            const float* vb = dyn + 8192 + buf * 4096;

            // ---- S-GEMM ----
            float sc[8][4];
#pragma unroll
            for (int nf = 0; nf < 8; nf++)
#pragma unroll
                for (int i = 0; i < 4; i++) sc[nf][i] = 0.f;

#pragma unroll
            for (int ks = 0; ks < 8; ks++) {
#pragma unroll
                for (int nf = 0; nf < 8; nf++) {
                    int key = 8 * nf + g;
                    uint32_t kb0 = __float_as_uint(kb[key * 64 + (((2 * ks    ) ^ g) << 2) + tg]);
                    uint32_t kb1 = __float_as_uint(kb[key * 64 + (((2 * ks + 1) ^ g) << 2) + tg]);
                    mma_tf32(sc[nf], qa[ks][0], qa[ks][1], qa[ks][2], qa[ks][3], kb0, kb1);
                }
            }

            // ---- bias + mask ----
#pragma unroll
            for (int nf = 0; nf < 8; nf++) {
                int c0 = s0 + 8 * nf + 2 * tg;
                {
                    float rbx = rb0[nf].x, rby = rb0[nf].y;
                    bool a0 = (c0     == irow0) || ((c0     < irow0) && (rbx > 0.f));
                    bool a1 = (c0 + 1 == irow0) || ((c0 + 1 < irow0) && (rby > 0.f));
                    sc[nf][0] = a0 ? sc[nf][0] * scale + rbx : -1e30f;
                    sc[nf][1] = a1 ? sc[nf][1] * scale + rby : -1e30f;
                }
                {
                    float rbx = rb1[nf].x, rby = rb1[nf].y;
                    bool a0 = (c0     == irow1) || ((c0     < irow1) && (rbx > 0.f));
                    bool a1 = (c0 + 1 == irow1) || ((c0 + 1 < irow1) && (rby > 0.f));
                    sc[nf][2] = a0 ? sc[nf][2] * scale + rbx : -1e30f;
                    sc[nf][3] = a1 ? sc[nf][3] * scale + rby : -1e30f;
                }
            }

            // ---- online softmax (warp-local) ----
            float t0 = -1e30f, t1 = -1e30f;
#pragma unroll
            for (int nf = 0; nf < 8; nf++) {
                t0 = fmaxf(t0, fmaxf(sc[nf][0], sc[nf][1]));
                t1 = fmaxf(t1, fmaxf(sc[nf][2], sc[nf][3]));
            }
            t0 = fmaxf(t0, __shfl_xor_sync(0xffffffffu, t0, 1));
            t0 = fmaxf(t0, __shfl_xor_sync(0xffffffffu, t0, 2));
            t1 = fmaxf(t1, __shfl_xor_sync(0xffffffffu, t1, 1));
            t1 = fmaxf(t1, __shfl_xor_sync(0xffffffffu, t1, 2));

            float mn0 = fmaxf(m0, t0), mn1 = fmaxf(m1, t1);
            float f0 = __expf(m0 - mn0), f1 = __expf(m1 - mn1);
            m0 = mn0; m1 = mn1;

            float s0sum = 0.f, s1sum = 0.f;
#pragma unroll
            for (int nf = 0; nf < 8; nf++) {
                float e;
                e = (sc[nf][0] > -1e29f) ? __expf(sc[nf][0] - mn0) : 0.f; sc[nf][0] = e; s0sum += e;
                e = (sc[nf][1] > -1e29f) ? __expf(sc[nf][1] - mn0) : 0.f; sc[nf][1] = e; s0sum += e;
                e = (sc[nf][2] > -1e29f) ? __expf(sc[nf][2] - mn1) : 0.f; sc[nf][2] = e; s1sum += e;
                e = (sc[nf][3] > -1e29f) ? __expf(sc[nf][3] - mn1) : 0.f; sc[nf][3] = e; s1sum += e;
            }
            s0sum += __shfl_xor_sync(0xffffffffu, s0sum, 1);
            s0sum += __shfl_xor_sync(0xffffffffu, s0sum, 2);
            s1sum += __shfl_xor_sync(0xffffffffu, s1sum, 1);
            s1sum += __shfl_xor_sync(0xffffffffu, s1sum, 2);
            l0 = l0 * f0 + s0sum;
            l1 = l1 * f1 + s1sum;

#pragma unroll
            for (int nf = 0; nf < 8; nf++) {
                o[nf][0] *= f0; o[nf][1] *= f0;
                o[nf][2] *= f1; o[nf][3] *= f1;
            }

            // ---- write P (tf32) into ps (warp-private rows) ----
#pragma unroll
            for (int nf = 0; nf < 8; nf++) {
                *(float2*)&ps[rl * 68 + 8 * nf + 2 * tg] =
                    make_float2(to_tf32(sc[nf][0]), to_tf32(sc[nf][1]));
                *(float2*)&ps[(rl + 8) * 68 + 8 * nf + 2 * tg] =
                    make_float2(to_tf32(sc[nf][2]), to_tf32(sc[nf][3]));
            }
            __syncwarp();

            // ---- O-GEMM: O += P * V ----
#pragma unroll
            for (int ks = 0; ks < 8; ks++) {
                uint32_t pa0 = __float_as_uint(ps[rl * 68       + 8 * ks + tg    ]);
                uint32_t pa1 = __float_as_uint(ps[(rl + 8) * 68 + 8 * ks + tg    ]);
                uint32_t pa2 = __float_as_uint(ps[rl * 68       + 8 * ks + tg + 4]);
                uint32_t pa3 = __float_as_uint(ps[(rl + 8) * 68 + 8 * ks + tg + 4]);
                const int key0 = 8 * ks + tg, key1 = key0 + 4;
#pragma unroll
                for (int nf = 0; nf < 8; nf++) {
                    int cv = (((2 * nf + (g >> 2)) ^ (tg << 1)) << 2) + (g & 3);
                    uint32_t vb0 = __float_as_uint(vb[key0 * 64 + cv]);
                    uint32_t vb1 = __float_as_uint(vb[key1 * 64 + cv]);
                    mma_tf32(o[nf], pa0, pa1, pa2, pa3, vb0, vb1);
                }
            }
        }

        // ---- epilogue: write UNNORMALIZED partial to scratch ----
        const int row0g = b * TT + irow0;
        const int row1g = b * TT + irow1;
        float* po0 = g_po + ((size_t)ch * NROWS + row0g) * HH + 2 * tg;
        float* po1 = g_po + ((size_t)ch * NROWS + row1g) * HH + 2 * tg;
#pragma unroll
        for (int nf = 0; nf < 8; nf++) {
            *(float2*)(po0 + 8 * nf) = make_float2(o[nf][0], o[nf][1]);
            *(float2*)(po1 + 8 * nf) = make_float2(o[nf][2], o[nf][3]);
        }
        if (tg == 0) {
            g_pml[ch * NROWS + row0g] = make_float2(m0, l0);
            g_pml[ch * NROWS + row1g] = make_float2(m1, l1);
        }
    }
}

// ---------------------------------------------------------------------------
// Merge partial-softmax chunks: out = (sum_c o_c * e^{m_c-M}) / (sum_c l_c * e^{m_c-M})
// ---------------------------------------------------------------------------
__global__ __launch_bounds__(256) void merge_kernel(float* __restrict__ out)
{
    const int idx = blockIdx.x * 256 + threadIdx.x;   // 0 .. 524287
    const int r   = idx >> 5;                         // global row
    const int h2  = (idx & 31) << 1;                  // col pair
    const int t   = r & (TT - 1);
    const int qt  = t >> 6;
    const int nc  = (qt >> 3) + 1;

    float2 ml[4];
    float M = -1e30f;
    for (int c = 0; c < nc; c++) {
        ml[c] = g_pml[c * NROWS + r];
        M = fmaxf(M, ml[c].x);
    }
    float a0 = 0.f, a1 = 0.f, l = 0.f;
    for (int c = 0; c < nc; c++) {
        float wgt = __expf(ml[c].x - M);
        float2 ov = *(const float2*)(g_po + ((size_t)c * NROWS + r) * HH + h2);
        a0 += ov.x * wgt;
        a1 += ov.y * wgt;
        l  += ml[c].y * wgt;
    }
    const float inv = 1.f / l;
    *(float2*)(out + (size_t)r * HH + h2) = make_float2(a0 * inv, a1 * inv);
}

extern "C" void kernel_launch(void* const* d_in, const int* in_sizes, int n_in,
                              void* d_out, int out_size)
{
    (void)in_sizes; (void)n_in; (void)out_size;
    const float* x     = (const float*)d_in[0];
    const float* Wq    = (const float*)d_in[1];
    const float* Wk    = (const float*)d_in[2];
    const float* Wv    = (const float*)d_in[3];
    const float* rbias = (const float*)d_in[4];

    const int attn_smem = 2 * 16384 + 2 * 16384 + 64 * 68 * 4 + 4;  // 82,948 B
    cudaFuncSetAttribute(attn_kernel,
                         cudaFuncAttributeMaxDynamicSharedMemorySize, attn_smem);

    qkv_mma_kernel<<<256, 256>>>(x, Wq, Wk, Wv);
    reset_ctr_kernel<<<1, 1>>>();
    attn_kernel<<<304, 128, attn_smem>>>(rbias);
    merge_kernel<<<(NROWS * HH / 2) / 256, 256>>>((float*)d_out);
}